// round 12
// baseline (speedup 1.0000x reference)
#include <cuda_runtime.h>
#include <cuda_bf16.h>
#include <cstdint>

// DotProductAttention B=8,H=8,N=2048,D=64 fp32 — R11.
// R8 numerics (3-pass bf16-split mma, __expf fixed-max softmax, exact pad-bias)
// restructured: 64-row q tiles, warps split keys (16 rows x 32 keys each),
// grid 2048 CTAs -> 6.92 waves (tail ~1% vs 13%), softmax fused into S loop,
// epilogue pairwise O/l merge through smem.

#define SM_QHI 0
#define SM_QLO 8192
#define SM_KV  16384            // 2 stages x 32KB: [KHI|KLO|VHI|VLO] 8KB each
#define STAGE  32768
#define SM_TOTAL (SM_KV + 2 * STAGE)   // 80KB

#define EXP_M10 4.5399929762e-05f      // e^-10 (pad-slot p value)

__device__ int g_cnt[8];
__device__ unsigned char KCH[1 << 24];   // 16MB each: [bh][slot][64 bf16]
__device__ unsigned char KCL[1 << 24];
__device__ unsigned char VCH[1 << 24];
__device__ unsigned char VCL[1 << 24];

// ---- helpers ----
__device__ __forceinline__ uint32_t smem_u32(const void* p) {
    uint32_t a;
    asm("{ .reg .u64 t; cvta.to.shared.u64 t, %1; cvt.u32.u64 %0, t; }" : "=r"(a) : "l"(p));
    return a;
}
__device__ __forceinline__ void split2(float a, float b, uint32_t& hi, uint32_t& lo) {
    uint32_t h;
    asm("cvt.rn.bf16x2.f32 %0, %1, %2;" : "=r"(h) : "f"(b), "f"(a));
    float ah = __uint_as_float(h << 16);
    float bh = __uint_as_float(h & 0xffff0000u);
    asm("cvt.rn.bf16x2.f32 %0, %1, %2;" : "=r"(lo) : "f"(b - bh), "f"(a - ah));
    hi = h;
}
__device__ __forceinline__ void mma_bf16(float* d, const uint32_t* a, const uint32_t* b) {
    asm volatile("mma.sync.aligned.m16n8k16.row.col.f32.bf16.bf16.f32 "
                 "{%0,%1,%2,%3}, {%4,%5,%6,%7}, {%8,%9}, {%0,%1,%2,%3};"
                 : "+f"(d[0]), "+f"(d[1]), "+f"(d[2]), "+f"(d[3])
                 : "r"(a[0]), "r"(a[1]), "r"(a[2]), "r"(a[3]), "r"(b[0]), "r"(b[1]));
}
__device__ __forceinline__ void ldsm2(uint32_t& r0, uint32_t& r1, uint32_t addr) {
    asm volatile("ldmatrix.sync.aligned.m8n8.x2.shared.b16 {%0,%1}, [%2];"
                 : "=r"(r0), "=r"(r1) : "r"(addr));
}
__device__ __forceinline__ void ldsm2t(uint32_t& r0, uint32_t& r1, uint32_t addr) {
    asm volatile("ldmatrix.sync.aligned.m8n8.x2.trans.shared.b16 {%0,%1}, [%2];"
                 : "=r"(r0), "=r"(r1) : "r"(addr));
}
__device__ __forceinline__ void ldsm4(uint32_t* r, uint32_t addr) {
    asm volatile("ldmatrix.sync.aligned.m8n8.x4.shared.b16 {%0,%1,%2,%3}, [%4];"
                 : "=r"(r[0]), "=r"(r[1]), "=r"(r[2]), "=r"(r[3]) : "r"(addr));
}

// ---- merged pre-pass: one block per (b,h) ----
__global__ void __launch_bounds__(1024)
prep_kv(const float* __restrict__ K, const float* __restrict__ V,
        const unsigned char* __restrict__ mraw)
{
    __shared__ int wsum[32];
    __shared__ int s_idx[2048];
    const int bh = blockIdx.x;                 // 0..63
    const int b  = bh >> 3;
    const int t  = threadIdx.x;                // 1024 threads
    const int lane = t & 31, w = t >> 5;

    int mynz = 0;
#pragma unroll
    for (int k = 0; k < 4; k++) {
        int i = t * 4 + k;
        if ((i & 3) && mraw[i]) mynz = 1;
    }
    const int is_u8 = __syncthreads_or(mynz);  // bool-as-u8 vs bool-as-i32

    int m0, m1;
    if (is_u8) {
        m0 = mraw[b * 2048 + 2 * t];
        m1 = mraw[b * 2048 + 2 * t + 1];
    } else {
        const int* mi = (const int*)mraw;
        m0 = mi[b * 2048 + 2 * t];
        m1 = mi[b * 2048 + 2 * t + 1];
    }
    const int f0 = (m0 == 0), f1 = (m1 == 0);
    const int pair = f0 + f1;

    int sc = pair;                             // inclusive warp scan
#pragma unroll
    for (int d = 1; d < 32; d <<= 1) {
        int v = __shfl_up_sync(0xffffffffu, sc, d);
        if (lane >= d) sc += v;
    }
    if (lane == 31) wsum[w] = sc;
    __syncthreads();
    if (w == 0) {
        int s2 = wsum[lane];
#pragma unroll
        for (int d = 1; d < 32; d <<= 1) {
            int u = __shfl_up_sync(0xffffffffu, s2, d);
            if (lane >= d) s2 += u;
        }
        wsum[lane] = s2;
    }
    __syncthreads();
    int base = (w ? wsum[w - 1] : 0) + sc - pair;
    if (f0) s_idx[base++] = 2 * t;
    if (f1) s_idx[base] = 2 * t + 1;
    const int cnt = wsum[31];
    if (t == 0) g_cnt[b] = cnt;
    __syncthreads();

    const int padded = (cnt + 63) & ~63;
    for (int idx = t; idx < padded * 16; idx += 1024) {
        const int slot = idx >> 4;
        const int c4   = (idx & 15) << 2;
        const size_t doff = ((((size_t)bh << 11) + slot) << 7) + c4 * 2;
        uint32_t kh0 = 0, kl0 = 0, kh1 = 0, kl1 = 0;
        uint32_t vh0 = 0, vl0 = 0, vh1 = 0, vl1 = 0;
        if (slot < cnt) {
            const int row = s_idx[slot];
            const float4 kk = *(const float4*)(K + ((((size_t)bh << 11) + row) << 6) + c4);
            const float4 vv = *(const float4*)(V + ((((size_t)bh << 11) + row) << 6) + c4);
            split2(kk.x, kk.y, kh0, kl0); split2(kk.z, kk.w, kh1, kl1);
            split2(vv.x, vv.y, vh0, vl0); split2(vv.z, vv.w, vh1, vl1);
        }
        *(uint2*)(KCH + doff) = make_uint2(kh0, kh1);
        *(uint2*)(KCL + doff) = make_uint2(kl0, kl1);
        *(uint2*)(VCH + doff) = make_uint2(vh0, vh1);
        *(uint2*)(VCL + doff) = make_uint2(vl0, vl1);
    }
}

// ---- cp.async staging of one 64-key tile (K/V hi/lo) into a smem stage ----
__device__ __forceinline__ void stage_tile(uint32_t sdst, int bh, int kv0, int tid)
{
#pragma unroll
    for (int it = 0; it < 8; it++) {
        const int tensor = it >> 1;
        const int cc = ((it & 1) << 8) + tid;            // 0..511
        const int r = cc >> 3, ch = cc & 7;
        const unsigned char* g = (tensor == 0) ? KCH : (tensor == 1) ? KCL
                               : (tensor == 2) ? VCH : VCL;
        const unsigned char* src = g + ((((size_t)bh << 11) + kv0 + r) << 7) + (ch << 4);
        uint32_t dst = sdst + tensor * 8192 + r * 128 + ((ch ^ (r & 7)) << 4);
        asm volatile("cp.async.cg.shared.global [%0], [%1], 16;"
                     :: "r"(dst), "l"(src) : "memory");
    }
}
#define CP_COMMIT() asm volatile("cp.async.commit_group;" ::: "memory")
#define CP_WAIT0()  asm volatile("cp.async.wait_group 0;" ::: "memory")

// ---- main kernel: 256 threads, 8 warps; 64 q-rows; warp = 16 rows x 32 keys ----
__global__ void __launch_bounds__(256, 2)
attn_mma(const float* __restrict__ Q, float* __restrict__ out)
{
    extern __shared__ char smem[];
    const uint32_t sb = smem_u32(smem);

    const int tid  = threadIdx.x;
    const int warp = tid >> 5;
    const int lane = tid & 31;
    const int gid  = lane >> 2;
    const int tig  = lane & 3;
    const int R0   = (warp & 3) << 4;     // warp's 16 q-rows within tile
    const int koff = (warp >> 2) << 5;    // warp's 32-key half within kv tile

    const int bh = blockIdx.y;
    const int b  = bh >> 3;
    const int q0 = blockIdx.x << 6;       // 64-row q tile

    const int cnt    = g_cnt[b];
    const int ntiles = (cnt + 63) >> 6;

    const float* Qg = Q + ((((size_t)bh << 11) + q0) << 6);

    // stage tile 0 first (overlaps with Q conversion below)
    stage_tile(sb + SM_KV, bh, 0, tid);
    CP_COMMIT();

    // ---- Q -> smem (hi/lo bf16, XOR swizzle): 64 rows ----
#pragma unroll
    for (int it = 0; it < 4; it++) {
        int idx = it * 256 + tid;         // 1024 float4 slots: 64 rows x 16
        int r   = idx >> 4;
        int c4  = (idx & 15) << 2;
        float4 v = *(const float4*)(Qg + (r << 6) + c4);
        uint32_t h0, l0, h1, l1;
        split2(v.x, v.y, h0, l0);
        split2(v.z, v.w, h1, l1);
        uint32_t off = r * 128 + ((c4 * 2) ^ ((r & 7) << 4));
        *(uint2*)(smem + SM_QHI + off) = make_uint2(h0, h1);
        *(uint2*)(smem + SM_QLO + off) = make_uint2(l0, l1);
    }
    __syncthreads();

    // ---- Q A-fragments in registers for the whole kernel ----
    uint32_t qh[4][4], ql[4][4];
    {
        const int arow = R0 + (lane & 7) + ((lane >> 3) & 1) * 8;
        const int asw  = lane & 7;
#pragma unroll
        for (int kk = 0; kk < 4; kk++) {
            uint32_t off = arow * 128 + ((((2 * kk + (lane >> 4)) ^ asw)) << 4);
            ldsm4(qh[kk], sb + SM_QHI + off);
            ldsm4(ql[kk], sb + SM_QLO + off);
        }
    }

    float o[8][4];
#pragma unroll
    for (int j = 0; j < 8; j++)
#pragma unroll
        for (int e = 0; e < 4; e++) o[j][e] = 0.0f;
    float lsum_lo = 0.0f, lsum_hi = 0.0f;

    const int krow = lane & 7;
    const int ksel = (lane >> 3) & 1;
    const int vrow = (lane & 7) + ((lane >> 3) & 1) * 8;

    for (int kt = 0; kt < ntiles; kt++) {
        CP_WAIT0();
        __syncthreads();                  // tile kt visible; old buffer free
        if (kt + 1 < ntiles) {
            stage_tile(sb + SM_KV + ((kt + 1) & 1) * STAGE, bh, (kt + 1) << 6, tid);
            CP_COMMIT();
        }
        const uint32_t kb = sb + SM_KV + (kt & 1) * STAGE;  // KHI|KLO|VHI|VLO

        // ---- S = Q K^T over this warp's 32 keys, softmax fused per n8 tile ----
        float s[4][4];
#pragma unroll
        for (int j = 0; j < 4; j++) {
#pragma unroll
            for (int e = 0; e < 4; e++) s[j][e] = 0.0f;
#pragma unroll
            for (int kk = 0; kk < 4; kk++) {
                const int rr = koff + 8 * j + krow;
                uint32_t off = rr * 128 + (((2 * kk + ksel) ^ krow) << 4);
                uint32_t kbh[2], kbl[2];
                ldsm2(kbh[0], kbh[1], kb + off);
                ldsm2(kbl[0], kbl[1], kb + 8192 + off);
                mma_bf16(s[j], qh[kk], kbh);
                mma_bf16(s[j], qh[kk], kbl);
                mma_bf16(s[j], ql[kk], kbh);
            }
            // fused softmax: p = exp(10*tanh(s/8) - 10); pad slots give e^-10
#pragma unroll
            for (int e = 0; e < 4; e++) {
                float eu = __expf(0.25f * s[j][e]);
                float p  = __expf(-__fdividef(20.0f, eu + 1.0f));
                s[j][e] = p;
                if ((e & 2) == 0) lsum_lo += p; else lsum_hi += p;
            }
        }

        // ---- O += P V over this warp's 32 keys (2 k16 chunks) ----
#pragma unroll
        for (int kk = 0; kk < 2; kk++) {
            const int j0 = 2 * kk;
            uint32_t pah[4], pal[4];
            split2(s[j0][0],     s[j0][1],     pah[0], pal[0]);
            split2(s[j0][2],     s[j0][3],     pah[1], pal[1]);
            split2(s[j0 + 1][0], s[j0 + 1][1], pah[2], pal[2]);
            split2(s[j0 + 1][2], s[j0 + 1][3], pah[3], pal[3]);
#pragma unroll
            for (int j = 0; j < 8; j++) {
                const int rr = koff + 16 * kk + vrow;
                uint32_t off = rr * 128 + ((j ^ (vrow & 7)) << 4);
                uint32_t vbh[2], vbl[2];
                ldsm2t(vbh[0], vbh[1], kb + 16384 + off);
                ldsm2t(vbl[0], vbl[1], kb + 24576 + off);
                mma_bf16(o[j], pah, vbh);
                mma_bf16(o[j], pah, vbl);
                mma_bf16(o[j], pal, vbh);
            }
        }
    }

    // ---- epilogue: merge key-half partials (warp w & w+4), scale, store ----
    __syncthreads();                      // all stage-buffer reads complete

    // quad-reduce l partials (rows gid / gid+8 over this warp's 32 keys)
    lsum_lo += __shfl_xor_sync(0xffffffffu, lsum_lo, 1);
    lsum_lo += __shfl_xor_sync(0xffffffffu, lsum_lo, 2);
    lsum_hi += __shfl_xor_sync(0xffffffffu, lsum_hi, 1);
    lsum_hi += __shfl_xor_sync(0xffffffffu, lsum_hi, 2);

    float* lb = (float*)(smem + SM_QHI);  // Q smem dead: l partials [8 warps][16 rows]
    if (tig == 0) {
        lb[warp * 16 + gid]     = lsum_lo;
        lb[warp * 16 + 8 + gid] = lsum_hi;
    }
    if (warp >= 4) {                      // upper key-half: park O partials in smem
        float* ob = (float*)(smem + SM_KV + (warp - 4) * 4096);  // [16 rows][64 cols]
#pragma unroll
        for (int j = 0; j < 8; j++) {
            int col = 8 * j + 2 * tig;
            *(float2*)(ob + gid * 64 + col)       = make_float2(o[j][0], o[j][1]);
            *(float2*)(ob + (gid + 8) * 64 + col) = make_float2(o[j][2], o[j][3]);
        }
    }
    __syncthreads();

    if (warp < 4) {
        const float padbias = (float)(ntiles * 64 - cnt) * EXP_M10;
        const float inv_lo = 1.0f / (lb[warp * 16 + gid] + lb[(warp + 4) * 16 + gid] - padbias);
        const float inv_hi = 1.0f / (lb[warp * 16 + 8 + gid] + lb[(warp + 4) * 16 + 8 + gid] - padbias);
        const float* pb = (const float*)(smem + SM_KV + warp * 4096);
        const size_t row_lo = ((size_t)bh << 11) + q0 + R0 + gid;
        const size_t row_hi = row_lo + 8;
#pragma unroll
        for (int j = 0; j < 8; j++) {
            int col = 8 * j + 2 * tig;
            float2 plo = *(const float2*)(pb + gid * 64 + col);
            float2 phi = *(const float2*)(pb + (gid + 8) * 64 + col);
            *(float2*)(out + row_lo * 64 + col) =
                make_float2((o[j][0] + plo.x) * inv_lo, (o[j][1] + plo.y) * inv_lo);
            *(float2*)(out + row_hi * 64 + col) =
                make_float2((o[j][2] + phi.x) * inv_hi, (o[j][3] + phi.y) * inv_hi);
        }
    }
}

extern "C" void kernel_launch(void* const* d_in, const int* in_sizes, int n_in,
                              void* d_out, int out_size)
{
    const float* Q = (const float*)d_in[0];
    const float* K = (const float*)d_in[1];
    const float* V = (const float*)d_in[2];
    const unsigned char* mraw = (const unsigned char*)d_in[3];
    float* out = (float*)d_out;

    prep_kv<<<64, 1024>>>(K, V, mraw);

    cudaFuncSetAttribute(attn_mma, cudaFuncAttributeMaxDynamicSharedMemorySize, SM_TOTAL);
    dim3 grid(32, 64);                    // (q tiles of 64, B*H)
    attn_mma<<<grid, 256, SM_TOTAL>>>(Q, out);
}

// round 13
// speedup vs baseline: 1.0043x; 1.0043x over previous
#include <cuda_runtime.h>
#include <cuda_bf16.h>
#include <cstdint>

// DotProductAttention B=8,H=8,N=2048,D=64 fp32 — R12.
// R11 numerics/layout, but the per-tile CTA barrier is replaced by two
// decoupled 4-warp groups (key halves), each with group-private cp.async
// double-buffered staging + named-barrier sync. 4 independent rhythms/SM
// (2 CTAs x 2 groups) -> softmax(MUFU) bursts overlap other groups' MMAs.

#define SM_QHI 0
#define SM_QLO 8192
#define SM_GRP 16384            // 2 groups x 2 stages x 16KB
#define GSTAGE 16384            // per-stage: [KH 4K | KL 4K | VH 4K | VL 4K]
#define SM_TOTAL (SM_GRP + 2 * 2 * GSTAGE)   // 80KB

#define EXP_M10 4.5399929762e-05f      // e^-10 (pad-slot p value)

__device__ int g_cnt[8];
__device__ unsigned char KCH[1 << 24];   // 16MB each: [bh][slot][64 bf16]
__device__ unsigned char KCL[1 << 24];
__device__ unsigned char VCH[1 << 24];
__device__ unsigned char VCL[1 << 24];

// ---- helpers ----
__device__ __forceinline__ uint32_t smem_u32(const void* p) {
    uint32_t a;
    asm("{ .reg .u64 t; cvta.to.shared.u64 t, %1; cvt.u32.u64 %0, t; }" : "=r"(a) : "l"(p));
    return a;
}
__device__ __forceinline__ void split2(float a, float b, uint32_t& hi, uint32_t& lo) {
    uint32_t h;
    asm("cvt.rn.bf16x2.f32 %0, %1, %2;" : "=r"(h) : "f"(b), "f"(a));
    float ah = __uint_as_float(h << 16);
    float bh = __uint_as_float(h & 0xffff0000u);
    asm("cvt.rn.bf16x2.f32 %0, %1, %2;" : "=r"(lo) : "f"(b - bh), "f"(a - ah));
    hi = h;
}
__device__ __forceinline__ void mma_bf16(float* d, const uint32_t* a, const uint32_t* b) {
    asm volatile("mma.sync.aligned.m16n8k16.row.col.f32.bf16.bf16.f32 "
                 "{%0,%1,%2,%3}, {%4,%5,%6,%7}, {%8,%9}, {%0,%1,%2,%3};"
                 : "+f"(d[0]), "+f"(d[1]), "+f"(d[2]), "+f"(d[3])
                 : "r"(a[0]), "r"(a[1]), "r"(a[2]), "r"(a[3]), "r"(b[0]), "r"(b[1]));
}
__device__ __forceinline__ void ldsm2(uint32_t& r0, uint32_t& r1, uint32_t addr) {
    asm volatile("ldmatrix.sync.aligned.m8n8.x2.shared.b16 {%0,%1}, [%2];"
                 : "=r"(r0), "=r"(r1) : "r"(addr));
}
__device__ __forceinline__ void ldsm2t(uint32_t& r0, uint32_t& r1, uint32_t addr) {
    asm volatile("ldmatrix.sync.aligned.m8n8.x2.trans.shared.b16 {%0,%1}, [%2];"
                 : "=r"(r0), "=r"(r1) : "r"(addr));
}
__device__ __forceinline__ void ldsm4(uint32_t* r, uint32_t addr) {
    asm volatile("ldmatrix.sync.aligned.m8n8.x4.shared.b16 {%0,%1,%2,%3}, [%4];"
                 : "=r"(r[0]), "=r"(r[1]), "=r"(r[2]), "=r"(r[3]) : "r"(addr));
}

// ---- merged pre-pass: one block per (b,h) ----
__global__ void __launch_bounds__(1024)
prep_kv(const float* __restrict__ K, const float* __restrict__ V,
        const unsigned char* __restrict__ mraw)
{
    __shared__ int wsum[32];
    __shared__ int s_idx[2048];
    const int bh = blockIdx.x;                 // 0..63
    const int b  = bh >> 3;
    const int t  = threadIdx.x;                // 1024 threads
    const int lane = t & 31, w = t >> 5;

    int mynz = 0;
#pragma unroll
    for (int k = 0; k < 4; k++) {
        int i = t * 4 + k;
        if ((i & 3) && mraw[i]) mynz = 1;
    }
    const int is_u8 = __syncthreads_or(mynz);  // bool-as-u8 vs bool-as-i32

    int m0, m1;
    if (is_u8) {
        m0 = mraw[b * 2048 + 2 * t];
        m1 = mraw[b * 2048 + 2 * t + 1];
    } else {
        const int* mi = (const int*)mraw;
        m0 = mi[b * 2048 + 2 * t];
        m1 = mi[b * 2048 + 2 * t + 1];
    }
    const int f0 = (m0 == 0), f1 = (m1 == 0);
    const int pair = f0 + f1;

    int sc = pair;                             // inclusive warp scan
#pragma unroll
    for (int d = 1; d < 32; d <<= 1) {
        int v = __shfl_up_sync(0xffffffffu, sc, d);
        if (lane >= d) sc += v;
    }
    if (lane == 31) wsum[w] = sc;
    __syncthreads();
    if (w == 0) {
        int s2 = wsum[lane];
#pragma unroll
        for (int d = 1; d < 32; d <<= 1) {
            int u = __shfl_up_sync(0xffffffffu, s2, d);
            if (lane >= d) s2 += u;
        }
        wsum[lane] = s2;
    }
    __syncthreads();
    int base = (w ? wsum[w - 1] : 0) + sc - pair;
    if (f0) s_idx[base++] = 2 * t;
    if (f1) s_idx[base] = 2 * t + 1;
    const int cnt = wsum[31];
    if (t == 0) g_cnt[b] = cnt;
    __syncthreads();

    const int padded = (cnt + 63) & ~63;
    for (int idx = t; idx < padded * 16; idx += 1024) {
        const int slot = idx >> 4;
        const int c4   = (idx & 15) << 2;
        const size_t doff = ((((size_t)bh << 11) + slot) << 7) + c4 * 2;
        uint32_t kh0 = 0, kl0 = 0, kh1 = 0, kl1 = 0;
        uint32_t vh0 = 0, vl0 = 0, vh1 = 0, vl1 = 0;
        if (slot < cnt) {
            const int row = s_idx[slot];
            const float4 kk = *(const float4*)(K + ((((size_t)bh << 11) + row) << 6) + c4);
            const float4 vv = *(const float4*)(V + ((((size_t)bh << 11) + row) << 6) + c4);
            split2(kk.x, kk.y, kh0, kl0); split2(kk.z, kk.w, kh1, kl1);
            split2(vv.x, vv.y, vh0, vl0); split2(vv.z, vv.w, vh1, vl1);
        }
        *(uint2*)(KCH + doff) = make_uint2(kh0, kh1);
        *(uint2*)(KCL + doff) = make_uint2(kl0, kl1);
        *(uint2*)(VCH + doff) = make_uint2(vh0, vh1);
        *(uint2*)(VCL + doff) = make_uint2(vl0, vl1);
    }
}

// ---- group-private cp.async staging: 32-key half-tile (K/V hi/lo, 16KB) ----
// t128 in [0,128): 1024 16B-chunks / 128 threads = 8 each.
__device__ __forceinline__ void stage_grp(uint32_t gdst, int bh, int slot0, int t128)
{
#pragma unroll
    for (int it = 0; it < 8; it++) {
        const int tensor = it >> 1;                      // KH,KL,VH,VL
        const int cc = ((it & 1) << 7) + t128;           // 0..255
        const int r = cc >> 3, ch = cc & 7;              // r: 0..31 local key
        const unsigned char* g = (tensor == 0) ? KCH : (tensor == 1) ? KCL
                               : (tensor == 2) ? VCH : VCL;
        const unsigned char* src = g + ((((size_t)bh << 11) + slot0 + r) << 7) + (ch << 4);
        uint32_t dst = gdst + tensor * 4096 + r * 128 + ((ch ^ (r & 7)) << 4);
        asm volatile("cp.async.cg.shared.global [%0], [%1], 16;"
                     :: "r"(dst), "l"(src) : "memory");
    }
}
#define CP_COMMIT() asm volatile("cp.async.commit_group;" ::: "memory")
#define CP_WAIT0()  asm volatile("cp.async.wait_group 0;" ::: "memory")
#define GBAR(id)    asm volatile("bar.sync %0, 128;" :: "r"(id) : "memory")

// ---- main kernel: 256 threads, 8 warps; 64 q-rows; warp = 16 rows x 32 keys ----
__global__ void __launch_bounds__(256, 2)
attn_mma(const float* __restrict__ Q, float* __restrict__ out)
{
    extern __shared__ char smem[];
    const uint32_t sb = smem_u32(smem);

    const int tid  = threadIdx.x;
    const int warp = tid >> 5;
    const int lane = tid & 31;
    const int gid  = lane >> 2;
    const int tig  = lane & 3;
    const int R0   = (warp & 3) << 4;     // warp's 16 q-rows within tile
    const int half = warp >> 2;           // group / key-half
    const int t128 = tid & 127;

    const int bh = blockIdx.y;
    const int b  = bh >> 3;
    const int q0 = blockIdx.x << 6;       // 64-row q tile

    const int cnt    = g_cnt[b];
    const int ntiles = (cnt + 63) >> 6;

    const float* Qg = Q + ((((size_t)bh << 11) + q0) << 6);
    const uint32_t gbase = sb + SM_GRP + half * (2 * GSTAGE);

    // stage this group's half of tile 0 (overlaps Q conversion)
    stage_grp(gbase, bh, (half << 5), t128);
    CP_COMMIT();

    // ---- Q -> smem (hi/lo bf16, XOR swizzle): 64 rows ----
#pragma unroll
    for (int it = 0; it < 4; it++) {
        int idx = it * 256 + tid;         // 1024 float4 slots: 64 rows x 16
        int r   = idx >> 4;
        int c4  = (idx & 15) << 2;
        float4 v = *(const float4*)(Qg + (r << 6) + c4);
        uint32_t h0, l0, h1, l1;
        split2(v.x, v.y, h0, l0);
        split2(v.z, v.w, h1, l1);
        uint32_t off = r * 128 + ((c4 * 2) ^ ((r & 7) << 4));
        *(uint2*)(smem + SM_QHI + off) = make_uint2(h0, h1);
        *(uint2*)(smem + SM_QLO + off) = make_uint2(l0, l1);
    }
    __syncthreads();

    // ---- Q A-fragments in registers for the whole kernel ----
    uint32_t qh[4][4], ql[4][4];
    {
        const int arow = R0 + (lane & 7) + ((lane >> 3) & 1) * 8;
        const int asw  = lane & 7;
#pragma unroll
        for (int kk = 0; kk < 4; kk++) {
            uint32_t off = arow * 128 + ((((2 * kk + (lane >> 4)) ^ asw)) << 4);
            ldsm4(qh[kk], sb + SM_QHI + off);
            ldsm4(ql[kk], sb + SM_QLO + off);
        }
    }

    float o[8][4];
#pragma unroll
    for (int j = 0; j < 8; j++)
#pragma unroll
        for (int e = 0; e < 4; e++) o[j][e] = 0.0f;
    float lsum_lo = 0.0f, lsum_hi = 0.0f;

    const int krow = lane & 7;
    const int ksel = (lane >> 3) & 1;
    const int vrow = (lane & 7) + ((lane >> 3) & 1) * 8;

    for (int kt = 0; kt < ntiles; kt++) {
        CP_WAIT0();                       // this thread's stage loads done
        GBAR(half + 1);                   // group barrier: stage visible, old free
        if (kt + 1 < ntiles) {
            stage_grp(gbase + (((kt + 1) & 1) * GSTAGE), bh,
                      ((kt + 1) << 6) + (half << 5), t128);
            CP_COMMIT();
        }
        const uint32_t kb = gbase + (kt & 1) * GSTAGE;  // KH|KL|VH|VL (4KB each)

        // ---- S = Q K^T over this group's 32 keys, softmax fused per n8 tile ----
        float s[4][4];
#pragma unroll
        for (int j = 0; j < 4; j++) {
#pragma unroll
            for (int e = 0; e < 4; e++) s[j][e] = 0.0f;
#pragma unroll
            for (int kk = 0; kk < 4; kk++) {
                const int rr = 8 * j + krow;            // local key row
                uint32_t off = rr * 128 + (((2 * kk + ksel) ^ krow) << 4);
                uint32_t kbh[2], kbl[2];
                ldsm2(kbh[0], kbh[1], kb + off);
                ldsm2(kbl[0], kbl[1], kb + 4096 + off);
                mma_bf16(s[j], qh[kk], kbh);
                mma_bf16(s[j], qh[kk], kbl);
                mma_bf16(s[j], ql[kk], kbh);
            }
            // fused softmax: p = exp(10*tanh(s/8) - 10); pad slots give e^-10
#pragma unroll
            for (int e = 0; e < 4; e++) {
                float eu = __expf(0.25f * s[j][e]);
                float p  = __expf(-__fdividef(20.0f, eu + 1.0f));
                s[j][e] = p;
                if ((e & 2) == 0) lsum_lo += p; else lsum_hi += p;
            }
        }

        // ---- O += P V over this group's 32 keys (2 k16 chunks) ----
#pragma unroll
        for (int kk = 0; kk < 2; kk++) {
            const int j0 = 2 * kk;
            uint32_t pah[4], pal[4];
            split2(s[j0][0],     s[j0][1],     pah[0], pal[0]);
            split2(s[j0][2],     s[j0][3],     pah[1], pal[1]);
            split2(s[j0 + 1][0], s[j0 + 1][1], pah[2], pal[2]);
            split2(s[j0 + 1][2], s[j0 + 1][3], pah[3], pal[3]);
#pragma unroll
            for (int j = 0; j < 8; j++) {
                const int rr = 16 * kk + vrow;          // local key row
                uint32_t off = rr * 128 + ((j ^ (vrow & 7)) << 4);
                uint32_t vbh[2], vbl[2];
                ldsm2t(vbh[0], vbh[1], kb + 8192 + off);
                ldsm2t(vbl[0], vbl[1], kb + 12288 + off);
                mma_bf16(o[j], pah, vbh);
                mma_bf16(o[j], pah, vbl);
                mma_bf16(o[j], pal, vbh);
            }
        }
    }

    // ---- epilogue: merge key-half partials (warp w & w+4), scale, store ----
    __syncthreads();                      // both groups done; stages reusable

    lsum_lo += __shfl_xor_sync(0xffffffffu, lsum_lo, 1);
    lsum_lo += __shfl_xor_sync(0xffffffffu, lsum_lo, 2);
    lsum_hi += __shfl_xor_sync(0xffffffffu, lsum_hi, 1);
    lsum_hi += __shfl_xor_sync(0xffffffffu, lsum_hi, 2);

    float* lb = (float*)(smem + SM_QHI);  // Q smem dead: l partials [8 warps][16 rows]
    if (tig == 0) {
        lb[warp * 16 + gid]     = lsum_lo;
        lb[warp * 16 + 8 + gid] = lsum_hi;
    }
    if (warp >= 4) {                      // upper key-half: park O partials in smem
        float* ob = (float*)(smem + SM_GRP + (warp - 4) * 4096);  // [16 rows][64 cols]
#pragma unroll
        for (int j = 0; j < 8; j++) {
            int col = 8 * j + 2 * tig;
            *(float2*)(ob + gid * 64 + col)       = make_float2(o[j][0], o[j][1]);
            *(float2*)(ob + (gid + 8) * 64 + col) = make_float2(o[j][2], o[j][3]);
        }
    }
    __syncthreads();

    if (warp < 4) {
        const float padbias = (float)(ntiles * 64 - cnt) * EXP_M10;
        const float inv_lo = 1.0f / (lb[warp * 16 + gid] + lb[(warp + 4) * 16 + gid] - padbias);
        const float inv_hi = 1.0f / (lb[warp * 16 + 8 + gid] + lb[(warp + 4) * 16 + 8 + gid] - padbias);
        const float* pb = (const float*)(smem + SM_GRP + warp * 4096);
        const size_t row_lo = ((size_t)bh << 11) + q0 + R0 + gid;
        const size_t row_hi = row_lo + 8;
#pragma unroll
        for (int j = 0; j < 8; j++) {
            int col = 8 * j + 2 * tig;
            float2 plo = *(const float2*)(pb + gid * 64 + col);
            float2 phi = *(const float2*)(pb + (gid + 8) * 64 + col);
            *(float2*)(out + row_lo * 64 + col) =
                make_float2((o[j][0] + plo.x) * inv_lo, (o[j][1] + plo.y) * inv_lo);
            *(float2*)(out + row_hi * 64 + col) =
                make_float2((o[j][2] + phi.x) * inv_hi, (o[j][3] + phi.y) * inv_hi);
        }
    }
}

extern "C" void kernel_launch(void* const* d_in, const int* in_sizes, int n_in,
                              void* d_out, int out_size)
{
    const float* Q = (const float*)d_in[0];
    const float* K = (const float*)d_in[1];
    const float* V = (const float*)d_in[2];
    const unsigned char* mraw = (const unsigned char*)d_in[3];
    float* out = (float*)d_out;

    prep_kv<<<64, 1024>>>(K, V, mraw);

    cudaFuncSetAttribute(attn_mma, cudaFuncAttributeMaxDynamicSharedMemorySize, SM_TOTAL);
    dim3 grid(32, 64);                    // (q tiles of 64, B*H)
    attn_mma<<<grid, 256, SM_TOTAL>>>(Q, out);
}

// round 15
// speedup vs baseline: 1.0795x; 1.0749x over previous
#include <cuda_runtime.h>
#include <cuda_bf16.h>
#include <cstdint>

// DotProductAttention B=8,H=8,N=2048,D=64 fp32 — R14 (= R13 resubmit; infra fail).
// R12 structure; changes:
//  (1) PV GEMM -> fp16 2-pass: P single fp16, V split fp16 hi/lo (was bf16
//      3-pass). 48->32 mma per warp-tile; total HMMA x5/6.
//  (2) S accumulator 2-chain split (4-deep + 8-deep RAW chains vs 12-deep).
// S GEMM stays bf16 3-pass (tanh x10 error amplification needs it).

#define SM_QHI 0
#define SM_QLO 8192
#define SM_GRP 16384            // 2 groups x 2 stages x 16KB
#define GSTAGE 16384            // per-stage: [KH 4K | KL 4K | VH 4K | VL 4K]
#define SM_TOTAL (SM_GRP + 2 * 2 * GSTAGE)   // 80KB

#define EXP_M10 4.5399929762e-05f      // e^-10 (pad-slot p value)

__device__ int g_cnt[8];
__device__ unsigned char KCH[1 << 24];   // bf16 hi  [bh][slot][64]
__device__ unsigned char KCL[1 << 24];   // bf16 lo
__device__ unsigned char VCH[1 << 24];   // fp16 hi
__device__ unsigned char VCL[1 << 24];   // fp16 lo

// ---- helpers ----
__device__ __forceinline__ uint32_t smem_u32(const void* p) {
    uint32_t a;
    asm("{ .reg .u64 t; cvta.to.shared.u64 t, %1; cvt.u32.u64 %0, t; }" : "=r"(a) : "l"(p));
    return a;
}
// bf16 hi/lo split, a->low half, b->high half
__device__ __forceinline__ void split2(float a, float b, uint32_t& hi, uint32_t& lo) {
    uint32_t h;
    asm("cvt.rn.bf16x2.f32 %0, %1, %2;" : "=r"(h) : "f"(b), "f"(a));
    float ah = __uint_as_float(h << 16);
    float bh = __uint_as_float(h & 0xffff0000u);
    asm("cvt.rn.bf16x2.f32 %0, %1, %2;" : "=r"(lo) : "f"(b - bh), "f"(a - ah));
    hi = h;
}
// fp16 hi/lo split, a->low half, b->high half
__device__ __forceinline__ void split2h(float a, float b, uint32_t& hi, uint32_t& lo) {
    uint32_t h;
    asm("cvt.rn.f16x2.f32 %0, %1, %2;" : "=r"(h) : "f"(b), "f"(a));
    float ah, bh;
    asm("{ .reg .b16 x, y; mov.b32 {x, y}, %2; cvt.f32.f16 %0, x; cvt.f32.f16 %1, y; }"
        : "=f"(ah), "=f"(bh) : "r"(h));
    asm("cvt.rn.f16x2.f32 %0, %1, %2;" : "=r"(lo) : "f"(b - bh), "f"(a - ah));
    hi = h;
}
__device__ __forceinline__ void mma_bf16(float* d, const uint32_t* a, const uint32_t* b) {
    asm volatile("mma.sync.aligned.m16n8k16.row.col.f32.bf16.bf16.f32 "
                 "{%0,%1,%2,%3}, {%4,%5,%6,%7}, {%8,%9}, {%0,%1,%2,%3};"
                 : "+f"(d[0]), "+f"(d[1]), "+f"(d[2]), "+f"(d[3])
                 : "r"(a[0]), "r"(a[1]), "r"(a[2]), "r"(a[3]), "r"(b[0]), "r"(b[1]));
}
__device__ __forceinline__ void mma_f16(float* d, const uint32_t* a, const uint32_t* b) {
    asm volatile("mma.sync.aligned.m16n8k16.row.col.f32.f16.f16.f32 "
                 "{%0,%1,%2,%3}, {%4,%5,%6,%7}, {%8,%9}, {%0,%1,%2,%3};"
                 : "+f"(d[0]), "+f"(d[1]), "+f"(d[2]), "+f"(d[3])
                 : "r"(a[0]), "r"(a[1]), "r"(a[2]), "r"(a[3]), "r"(b[0]), "r"(b[1]));
}
__device__ __forceinline__ void ldsm2(uint32_t& r0, uint32_t& r1, uint32_t addr) {
    asm volatile("ldmatrix.sync.aligned.m8n8.x2.shared.b16 {%0,%1}, [%2];"
                 : "=r"(r0), "=r"(r1) : "r"(addr));
}
__device__ __forceinline__ void ldsm2t(uint32_t& r0, uint32_t& r1, uint32_t addr) {
    asm volatile("ldmatrix.sync.aligned.m8n8.x2.trans.shared.b16 {%0,%1}, [%2];"
                 : "=r"(r0), "=r"(r1) : "r"(addr));
}
__device__ __forceinline__ void ldsm4(uint32_t* r, uint32_t addr) {
    asm volatile("ldmatrix.sync.aligned.m8n8.x4.shared.b16 {%0,%1,%2,%3}, [%4];"
                 : "=r"(r[0]), "=r"(r[1]), "=r"(r[2]), "=r"(r[3]) : "r"(addr));
}

// ---- merged pre-pass: one block per (b,h) ----
__global__ void __launch_bounds__(1024)
prep_kv(const float* __restrict__ K, const float* __restrict__ V,
        const unsigned char* __restrict__ mraw)
{
    __shared__ int wsum[32];
    __shared__ int s_idx[2048];
    const int bh = blockIdx.x;                 // 0..63
    const int b  = bh >> 3;
    const int t  = threadIdx.x;                // 1024 threads
    const int lane = t & 31, w = t >> 5;

    int mynz = 0;
#pragma unroll
    for (int k = 0; k < 4; k++) {
        int i = t * 4 + k;
        if ((i & 3) && mraw[i]) mynz = 1;
    }
    const int is_u8 = __syncthreads_or(mynz);  // bool-as-u8 vs bool-as-i32

    int m0, m1;
    if (is_u8) {
        m0 = mraw[b * 2048 + 2 * t];
        m1 = mraw[b * 2048 + 2 * t + 1];
    } else {
        const int* mi = (const int*)mraw;
        m0 = mi[b * 2048 + 2 * t];
        m1 = mi[b * 2048 + 2 * t + 1];
    }
    const int f0 = (m0 == 0), f1 = (m1 == 0);
    const int pair = f0 + f1;

    int sc = pair;                             // inclusive warp scan
#pragma unroll
    for (int d = 1; d < 32; d <<= 1) {
        int v = __shfl_up_sync(0xffffffffu, sc, d);
        if (lane >= d) sc += v;
    }
    if (lane == 31) wsum[w] = sc;
    __syncthreads();
    if (w == 0) {
        int s2 = wsum[lane];
#pragma unroll
        for (int d = 1; d < 32; d <<= 1) {
            int u = __shfl_up_sync(0xffffffffu, s2, d);
            if (lane >= d) s2 += u;
        }
        wsum[lane] = s2;
    }
    __syncthreads();
    int base = (w ? wsum[w - 1] : 0) + sc - pair;
    if (f0) s_idx[base++] = 2 * t;
    if (f1) s_idx[base] = 2 * t + 1;
    const int cnt = wsum[31];
    if (t == 0) g_cnt[b] = cnt;
    __syncthreads();

    const int padded = (cnt + 63) & ~63;
    for (int idx = t; idx < padded * 16; idx += 1024) {
        const int slot = idx >> 4;
        const int c4   = (idx & 15) << 2;
        const size_t doff = ((((size_t)bh << 11) + slot) << 7) + c4 * 2;
        uint32_t kh0 = 0, kl0 = 0, kh1 = 0, kl1 = 0;
        uint32_t vh0 = 0, vl0 = 0, vh1 = 0, vl1 = 0;
        if (slot < cnt) {
            const int row = s_idx[slot];
            const float4 kk = *(const float4*)(K + ((((size_t)bh << 11) + row) << 6) + c4);
            const float4 vv = *(const float4*)(V + ((((size_t)bh << 11) + row) << 6) + c4);
            split2(kk.x, kk.y, kh0, kl0);  split2(kk.z, kk.w, kh1, kl1);    // bf16
            split2h(vv.x, vv.y, vh0, vl0); split2h(vv.z, vv.w, vh1, vl1);   // fp16
        }
        *(uint2*)(KCH + doff) = make_uint2(kh0, kh1);
        *(uint2*)(KCL + doff) = make_uint2(kl0, kl1);
        *(uint2*)(VCH + doff) = make_uint2(vh0, vh1);
        *(uint2*)(VCL + doff) = make_uint2(vl0, vl1);
    }
}

// ---- group-private cp.async staging: 32-key half-tile (K/V hi/lo, 16KB) ----
__device__ __forceinline__ void stage_grp(uint32_t gdst, int bh, int slot0, int t128)
{
#pragma unroll
    for (int it = 0; it < 8; it++) {
        const int tensor = it >> 1;                      // KH,KL,VH,VL
        const int cc = ((it & 1) << 7) + t128;           // 0..255
        const int r = cc >> 3, ch = cc & 7;              // r: 0..31 local key
        const unsigned char* g = (tensor == 0) ? KCH : (tensor == 1) ? KCL
                               : (tensor == 2) ? VCH : VCL;
        const unsigned char* src = g + ((((size_t)bh << 11) + slot0 + r) << 7) + (ch << 4);
        uint32_t dst = gdst + tensor * 4096 + r * 128 + ((ch ^ (r & 7)) << 4);
        asm volatile("cp.async.cg.shared.global [%0], [%1], 16;"
                     :: "r"(dst), "l"(src) : "memory");
    }
}
#define CP_COMMIT() asm volatile("cp.async.commit_group;" ::: "memory")
#define CP_WAIT0()  asm volatile("cp.async.wait_group 0;" ::: "memory")
#define GBAR(id)    asm volatile("bar.sync %0, 128;" :: "r"(id) : "memory")

// ---- main kernel: 256 threads, 8 warps; 64 q-rows; warp = 16 rows x 32 keys ----
__global__ void __launch_bounds__(256, 2)
attn_mma(const float* __restrict__ Q, float* __restrict__ out)
{
    extern __shared__ char smem[];
    const uint32_t sb = smem_u32(smem);

    const int tid  = threadIdx.x;
    const int warp = tid >> 5;
    const int lane = tid & 31;
    const int gid  = lane >> 2;
    const int tig  = lane & 3;
    const int R0   = (warp & 3) << 4;     // warp's 16 q-rows within tile
    const int half = warp >> 2;           // group / key-half
    const int t128 = tid & 127;

    const int bh = blockIdx.y;
    const int b  = bh >> 3;
    const int q0 = blockIdx.x << 6;       // 64-row q tile

    const int cnt    = g_cnt[b];
    const int ntiles = (cnt + 63) >> 6;

    const float* Qg = Q + ((((size_t)bh << 11) + q0) << 6);
    const uint32_t gbase = sb + SM_GRP + half * (2 * GSTAGE);

    stage_grp(gbase, bh, (half << 5), t128);
    CP_COMMIT();

    // ---- Q -> smem (hi/lo bf16, XOR swizzle): 64 rows ----
#pragma unroll
    for (int it = 0; it < 4; it++) {
        int idx = it * 256 + tid;
        int r   = idx >> 4;
        int c4  = (idx & 15) << 2;
        float4 v = *(const float4*)(Qg + (r << 6) + c4);
        uint32_t h0, l0, h1, l1;
        split2(v.x, v.y, h0, l0);
        split2(v.z, v.w, h1, l1);
        uint32_t off = r * 128 + ((c4 * 2) ^ ((r & 7) << 4));
        *(uint2*)(smem + SM_QHI + off) = make_uint2(h0, h1);
        *(uint2*)(smem + SM_QLO + off) = make_uint2(l0, l1);
    }
    __syncthreads();

    // ---- Q A-fragments in registers for the whole kernel ----
    uint32_t qh[4][4], ql[4][4];
    {
        const int arow = R0 + (lane & 7) + ((lane >> 3) & 1) * 8;
        const int asw  = lane & 7;
#pragma unroll
        for (int kk = 0; kk < 4; kk++) {
            uint32_t off = arow * 128 + ((((2 * kk + (lane >> 4)) ^ asw)) << 4);
            ldsm4(qh[kk], sb + SM_QHI + off);
            ldsm4(ql[kk], sb + SM_QLO + off);
        }
    }

    float o[8][4];
#pragma unroll
    for (int j = 0; j < 8; j++)
#pragma unroll
        for (int e = 0; e < 4; e++) o[j][e] = 0.0f;
    float lsum_lo = 0.0f, lsum_hi = 0.0f;

    const int krow = lane & 7;
    const int ksel = (lane >> 3) & 1;
    const int vrow = (lane & 7) + ((lane >> 3) & 1) * 8;

    for (int kt = 0; kt < ntiles; kt++) {
        CP_WAIT0();
        GBAR(half + 1);                   // group barrier: stage visible, old free
        if (kt + 1 < ntiles) {
            stage_grp(gbase + (((kt + 1) & 1) * GSTAGE), bh,
                      ((kt + 1) << 6) + (half << 5), t128);
            CP_COMMIT();
        }
        const uint32_t kb = gbase + (kt & 1) * GSTAGE;  // KH|KL|VH|VL (4KB each)

        // ---- S = Q K^T (bf16 3-pass, 2 independent accumulator chains) ----
        float s[4][4];
#pragma unroll
        for (int j = 0; j < 4; j++) {
            float sa[4] = {0.0f, 0.0f, 0.0f, 0.0f};
            float sc2[4] = {0.0f, 0.0f, 0.0f, 0.0f};
#pragma unroll
            for (int kk = 0; kk < 4; kk++) {
                const int rr = 8 * j + krow;
                uint32_t off = rr * 128 + (((2 * kk + ksel) ^ krow) << 4);
                uint32_t kbh[2], kbl[2];
                ldsm2(kbh[0], kbh[1], kb + off);
                ldsm2(kbl[0], kbl[1], kb + 4096 + off);
                mma_bf16(sa,  qh[kk], kbh);   // chain A: 4-deep
                mma_bf16(sc2, qh[kk], kbl);   // chain B: 8-deep
                mma_bf16(sc2, ql[kk], kbh);
            }
            // fused softmax: p = exp(10*tanh(s/8) - 10); pad slots give e^-10
#pragma unroll
            for (int e = 0; e < 4; e++) {
                float sv = sa[e] + sc2[e];
                float eu = __expf(0.25f * sv);
                float p  = __expf(-__fdividef(20.0f, eu + 1.0f));
                s[j][e] = p;
                if ((e & 2) == 0) lsum_lo += p; else lsum_hi += p;
            }
        }

        // ---- O += P V (fp16 2-pass: P single fp16, V hi/lo) ----
#pragma unroll
        for (int kk = 0; kk < 2; kk++) {
            const int j0 = 2 * kk;
            uint32_t pa[4];
            asm("cvt.rn.f16x2.f32 %0, %1, %2;" : "=r"(pa[0]) : "f"(s[j0][1]),     "f"(s[j0][0]));
            asm("cvt.rn.f16x2.f32 %0, %1, %2;" : "=r"(pa[1]) : "f"(s[j0][3]),     "f"(s[j0][2]));
            asm("cvt.rn.f16x2.f32 %0, %1, %2;" : "=r"(pa[2]) : "f"(s[j0 + 1][1]), "f"(s[j0 + 1][0]));
            asm("cvt.rn.f16x2.f32 %0, %1, %2;" : "=r"(pa[3]) : "f"(s[j0 + 1][3]), "f"(s[j0 + 1][2]));
#pragma unroll
            for (int j = 0; j < 8; j++) {
                const int rr = 16 * kk + vrow;
                uint32_t off = rr * 128 + ((j ^ (vrow & 7)) << 4);
                uint32_t vbh[2], vbl[2];
                ldsm2t(vbh[0], vbh[1], kb + 8192 + off);
                ldsm2t(vbl[0], vbl[1], kb + 12288 + off);
                mma_f16(o[j], pa, vbh);
                mma_f16(o[j], pa, vbl);
            }
        }
    }

    // ---- epilogue: merge key-half partials (warp w & w+4), scale, store ----
    __syncthreads();

    lsum_lo += __shfl_xor_sync(0xffffffffu, lsum_lo, 1);
    lsum_lo += __shfl_xor_sync(0xffffffffu, lsum_lo, 2);
    lsum_hi += __shfl_xor_sync(0xffffffffu, lsum_hi, 1);
    lsum_hi += __shfl_xor_sync(0xffffffffu, lsum_hi, 2);

    float* lb = (float*)(smem + SM_QHI);
    if (tig == 0) {
        lb[warp * 16 + gid]     = lsum_lo;
        lb[warp * 16 + 8 + gid] = lsum_hi;
    }
    if (warp >= 4) {
        float* ob = (float*)(smem + SM_GRP + (warp - 4) * 4096);
#pragma unroll
        for (int j = 0; j < 8; j++) {
            int col = 8 * j + 2 * tig;
            *(float2*)(ob + gid * 64 + col)       = make_float2(o[j][0], o[j][1]);
            *(float2*)(ob + (gid + 8) * 64 + col) = make_float2(o[j][2], o[j][3]);
        }
    }
    __syncthreads();

    if (warp < 4) {
        const float padbias = (float)(ntiles * 64 - cnt) * EXP_M10;
        const float inv_lo = 1.0f / (lb[warp * 16 + gid] + lb[(warp + 4) * 16 + gid] - padbias);
        const float inv_hi = 1.0f / (lb[warp * 16 + 8 + gid] + lb[(warp + 4) * 16 + 8 + gid] - padbias);
        const float* pb = (const float*)(smem + SM_GRP + warp * 4096);
        const size_t row_lo = ((size_t)bh << 11) + q0 + R0 + gid;
        const size_t row_hi = row_lo + 8;
#pragma unroll
        for (int j = 0; j < 8; j++) {
            int col = 8 * j + 2 * tig;
            float2 plo = *(const float2*)(pb + gid * 64 + col);
            float2 phi = *(const float2*)(pb + (gid + 8) * 64 + col);
            *(float2*)(out + row_lo * 64 + col) =
                make_float2((o[j][0] + plo.x) * inv_lo, (o[j][1] + plo.y) * inv_lo);
            *(float2*)(out + row_hi * 64 + col) =
                make_float2((o[j][2] + phi.x) * inv_hi, (o[j][3] + phi.y) * inv_hi);
        }
    }
}

extern "C" void kernel_launch(void* const* d_in, const int* in_sizes, int n_in,
                              void* d_out, int out_size)
{
    const float* Q = (const float*)d_in[0];
    const float* K = (const float*)d_in[1];
    const float* V = (const float*)d_in[2];
    const unsigned char* mraw = (const unsigned char*)d_in[3];
    float* out = (float*)d_out;

    prep_kv<<<64, 1024>>>(K, V, mraw);

    cudaFuncSetAttribute(attn_mma, cudaFuncAttributeMaxDynamicSharedMemorySize, SM_TOTAL);
    dim3 grid(32, 64);                    // (q tiles of 64, B*H)
    attn_mma<<<grid, 256, SM_TOTAL>>>(Q, out);
}